// round 1
// baseline (speedup 1.0000x reference)
#include <cuda_runtime.h>
#include <cuda_bf16.h>

#define BB 4
#define NN 4096
#define CC 256
#define II 128
#define ROWS (BB*NN)          // 16384
#define SEG 128
#define NSEG (NN/SEG)         // 32
#define BN_EPS 1e-3f

// ---------------- scratch (static device allocations) ----------------
__device__ float d_vt[CC], d_vp[CC];
__device__ float d_ct[1], d_cp[1];
__device__ float d_scale[CC], d_shift[CC];
__device__ float d_g[ROWS*II];              // g_x  (8 MB)
__device__ float d_st[ROWS], d_sp[ROWS];
__device__ float d_tsort[ROWS];
__device__ int   d_tidx[ROWS];
__device__ float d_P1[ROWS*II];             // per-segment inclusive prefix of g_sorted
__device__ float d_P2[ROWS*II];             // per-segment inclusive prefix of t*g_sorted
__device__ float d_seg1[BB*NSEG*II], d_seg2[BB*NSEG*II];
__device__ float d_off1[BB*NSEG*II], d_off2[BB*NSEG*II];

// ---------------- K0: fold weights (vt = wt@wc_lo, vp = wp@wc_hi, BN fold) ----
__global__ void k_prep(const float* __restrict__ wt, const float* __restrict__ wp,
                       const float* __restrict__ wc,
                       const float* __restrict__ bt, const float* __restrict__ bp,
                       const float* __restrict__ gamma, const float* __restrict__ beta,
                       const float* __restrict__ bn_mean, const float* __restrict__ bn_var,
                       const float* __restrict__ bw) {
    int c = threadIdx.x;               // 0..255
    float at = 0.f, ap = 0.f;
    #pragma unroll 4
    for (int k = 0; k < II; k++) {
        at = fmaf(wt[c*II + k], wc[k], at);
        ap = fmaf(wp[c*II + k], wc[II + k], ap);
    }
    d_vt[c] = at;
    d_vp[c] = ap;
    float a = gamma[c] * rsqrtf(bn_var[c] + BN_EPS);
    d_scale[c] = a;
    d_shift[c] = (bw[c] - bn_mean[c]) * a + beta[c];
    if (c == 0) {
        float s = 0.f;
        for (int k = 0; k < II; k++) s = fmaf(bt[k], wc[k], s);
        d_ct[0] = s;
    }
    if (c == 1) {
        float s = 0.f;
        for (int k = 0; k < II; k++) s = fmaf(bp[k], wc[II + k], s);
        d_cp[0] = s;
    }
}

// ---------------- K1b: scalar scores st = x.vt + ct, sp = x.vp + cp -----------
__global__ void k_scores(const float* __restrict__ x) {
    int row  = blockIdx.x * 8 + (threadIdx.x >> 5);
    int lane = threadIdx.x & 31;
    const float* xr = x + (size_t)row * CC;
    float at = 0.f, ap = 0.f;
    #pragma unroll
    for (int k = lane; k < CC; k += 32) {
        float v = xr[k];
        at = fmaf(v, d_vt[k], at);
        ap = fmaf(v, d_vp[k], ap);
    }
    #pragma unroll
    for (int o = 16; o; o >>= 1) {
        at += __shfl_xor_sync(0xffffffffu, at, o);
        ap += __shfl_xor_sync(0xffffffffu, ap, o);
    }
    if (lane == 0) {
        d_st[row] = at + d_ct[0];
        d_sp[row] = ap + d_cp[0];
    }
}

// ---------------- K1: g = x @ wg + bg  (M=16384, N=128, K=256) ---------------
// BM=128, BN=128, BK=32, 256 threads, 8x8 per thread
__global__ __launch_bounds__(256) void k_gemm_g(const float* __restrict__ x,
                                                const float* __restrict__ wg,
                                                const float* __restrict__ bg) {
    __shared__ float As[32][129];   // [k][m], padded
    __shared__ float Bs[32][128];   // [k][n]
    const int r0   = blockIdx.x * 128;
    const int tid  = threadIdx.x;
    const int trow = tid >> 4;      // 0..15
    const int tcol = tid & 15;      // 0..15

    float acc[8][8];
    #pragma unroll
    for (int v = 0; v < 8; v++)
        #pragma unroll
        for (int u = 0; u < 8; u++) acc[v][u] = 0.f;

    for (int kk = 0; kk < CC; kk += 32) {
        // load A tile (x rows r0..r0+127, cols kk..kk+31), store transposed
        #pragma unroll
        for (int i = 0; i < 16; i++) {
            int e   = i * 256 + tid;
            int row = e >> 5, col = e & 31;
            As[col][row] = x[(size_t)(r0 + row) * CC + kk + col];
        }
        // load B tile (wg rows kk..kk+31, all 128 cols)
        #pragma unroll
        for (int i = 0; i < 16; i++) {
            int e  = i * 256 + tid;
            int kr = e >> 7, c = e & 127;
            Bs[kr][c] = wg[(kk + kr) * II + c];
        }
        __syncthreads();
        #pragma unroll
        for (int k = 0; k < 32; k++) {
            float av[8], bv[8];
            #pragma unroll
            for (int v = 0; v < 8; v++) av[v] = As[k][trow + 16 * v];
            #pragma unroll
            for (int u = 0; u < 8; u++) bv[u] = Bs[k][tcol + 16 * u];
            #pragma unroll
            for (int v = 0; v < 8; v++)
                #pragma unroll
                for (int u = 0; u < 8; u++) acc[v][u] = fmaf(av[v], bv[u], acc[v][u]);
        }
        __syncthreads();
    }
    float bgu[8];
    #pragma unroll
    for (int u = 0; u < 8; u++) bgu[u] = bg[tcol + 16 * u];
    #pragma unroll
    for (int v = 0; v < 8; v++) {
        int gr = r0 + trow + 16 * v;
        #pragma unroll
        for (int u = 0; u < 8; u++)
            d_g[(size_t)gr * II + tcol + 16 * u] = acc[v][u] + bgu[u];
    }
}

// ---------------- K2: per-batch bitonic sort of s_theta (descending) ---------
__global__ __launch_bounds__(1024) void k_sort() {
    __shared__ float sv[NN];
    __shared__ int   si[NN];
    const int b = blockIdx.x;
    const int t = threadIdx.x;
    for (int i = t; i < NN; i += 1024) { sv[i] = d_st[b * NN + i]; si[i] = i; }
    __syncthreads();
    for (int k = 2; k <= NN; k <<= 1) {
        for (int j = k >> 1; j > 0; j >>= 1) {
            for (int i = t; i < NN; i += 1024) {
                int ixj = i ^ j;
                if (ixj > i) {
                    bool desc = ((i & k) == 0);   // descending overall
                    float a = sv[i], c2 = sv[ixj];
                    bool sw = desc ? (a < c2) : (a > c2);
                    if (sw) {
                        sv[i] = c2; sv[ixj] = a;
                        int ti = si[i]; si[i] = si[ixj]; si[ixj] = ti;
                    }
                }
            }
            __syncthreads();
        }
    }
    for (int i = t; i < NN; i += 1024) {
        d_tsort[b * NN + i] = sv[i];
        d_tidx [b * NN + i] = si[i];
    }
}

// ---------------- K3: per-segment prefix sums of g_sorted and t*g_sorted -----
__global__ __launch_bounds__(128) void k_scanA() {
    const int b = blockIdx.y, s = blockIdx.x, d = threadIdx.x;
    const int base = b * NN + s * SEG;
    float a1 = 0.f, a2 = 0.f;
    for (int r = 0; r < SEG; r++) {
        int pos  = base + r;
        int j    = d_tidx[pos];
        float tv = d_tsort[pos];
        float gv = d_g[(size_t)(b * NN + j) * II + d];
        a1 += gv;
        a2 = fmaf(tv, gv, a2);
        d_P1[(size_t)pos * II + d] = a1;
        d_P2[(size_t)pos * II + d] = a2;
    }
    d_seg1[(b * NSEG + s) * II + d] = a1;
    d_seg2[(b * NSEG + s) * II + d] = a2;
}

// ---------------- K4: exclusive scan of segment totals ----------------------
__global__ __launch_bounds__(512) void k_scanB() {
    const int b = threadIdx.x >> 7, d = threadIdx.x & 127;
    float a1 = 0.f, a2 = 0.f;
    for (int s = 0; s < NSEG; s++) {
        int idx = (b * NSEG + s) * II + d;
        d_off1[idx] = a1;
        d_off2[idx] = a2;
        a1 += d_seg1[idx];
        a2 += d_seg2[idx];
    }
}

// ---------------- K5: lookup + final GEMM (y@ww) + BN + residual -------------
// BM=64 rows, all 256 cols; BK=16; 256 threads, 8x8 per thread
__global__ __launch_bounds__(256) void k_final(const float* __restrict__ x,
                                               const float* __restrict__ ww,
                                               float* __restrict__ out) {
    __shared__ float Ys[64][II];    // 32 KB
    __shared__ float Ws[16][256];   // 16 KB (overlaid with sps/ks in phase A)
    const int gr0 = blockIdx.x * 64;
    const int b   = gr0 / NN;
    const int tid = threadIdx.x;

    float* sps = (float*)Ws;        // 64 floats
    int*   ks  = (int*)(&Ws[1][0]); // 64 ints (disjoint region)

    // ---- phase A: per-row binary search for k_i, build y rows ----
    if (tid < 64) {
        int i    = gr0 + tid;
        float sp = d_sp[i];
        sps[tid] = sp;
        float tau = -sp;
        const float* ts = d_tsort + b * NN;
        int lo = 0, hi = NN;
        while (lo < hi) {
            int mid = (lo + hi) >> 1;
            if (ts[mid] > tau) lo = mid + 1; else hi = mid;
        }
        ks[tid] = lo;
    }
    __syncthreads();

    const float invn = 1.f / NN;
    #pragma unroll
    for (int e = tid; e < 64 * II; e += 256) {
        int rr = e >> 7, d = e & 127;
        int k  = ks[rr];
        float p1 = 0.f, p2 = 0.f;
        if (k > 0) {
            size_t idx = (size_t)(b * NN + k - 1) * II + d;
            int    so  = (b * NSEG + ((k - 1) >> 7)) * II + d;
            p1 = d_P1[idx] + d_off1[so];
            p2 = d_P2[idx] + d_off2[so];
        }
        Ys[rr][d] = (sps[rr] * p1 + p2) * invn;
    }
    __syncthreads();

    // ---- phase B: GEMM 64x256, K=128 ----
    const int trow = tid >> 5;   // 0..7
    const int tcol = tid & 31;   // 0..31
    float acc[8][8];
    #pragma unroll
    for (int v = 0; v < 8; v++)
        #pragma unroll
        for (int u = 0; u < 8; u++) acc[v][u] = 0.f;

    for (int kk = 0; kk < II; kk += 16) {
        __syncthreads();   // protect Ws overlay / previous iter
        #pragma unroll
        for (int i = 0; i < 16; i++) {
            int e  = i * 256 + tid;
            int kr = e >> 8, c = e & 255;
            Ws[kr][c] = ww[(kk + kr) * CC + c];
        }
        __syncthreads();
        #pragma unroll
        for (int k = 0; k < 16; k++) {
            float yv[8], wv[8];
            #pragma unroll
            for (int v = 0; v < 8; v++) yv[v] = Ys[trow + 8 * v][kk + k];
            #pragma unroll
            for (int u = 0; u < 8; u++) wv[u] = Ws[k][tcol + 32 * u];
            #pragma unroll
            for (int v = 0; v < 8; v++)
                #pragma unroll
                for (int u = 0; u < 8; u++) acc[v][u] = fmaf(yv[v], wv[u], acc[v][u]);
        }
    }

    float sc[8], sh[8];
    #pragma unroll
    for (int u = 0; u < 8; u++) {
        int c = tcol + 32 * u;
        sc[u] = d_scale[c];
        sh[u] = d_shift[c];
    }
    #pragma unroll
    for (int v = 0; v < 8; v++) {
        int gr = gr0 + trow + 8 * v;
        #pragma unroll
        for (int u = 0; u < 8; u++) {
            int c = tcol + 32 * u;
            size_t gi = (size_t)gr * CC + c;
            out[gi] = fmaf(acc[v][u], sc[u], sh[u]) + x[gi];
        }
    }
}

// ---------------- launch -----------------------------------------------------
extern "C" void kernel_launch(void* const* d_in, const int* in_sizes, int n_in,
                              void* d_out, int out_size) {
    const float* x      = (const float*)d_in[0];
    const float* wg     = (const float*)d_in[1];
    const float* bg     = (const float*)d_in[2];
    const float* wt     = (const float*)d_in[3];
    const float* bt     = (const float*)d_in[4];
    const float* wp     = (const float*)d_in[5];
    const float* bp     = (const float*)d_in[6];
    const float* wc     = (const float*)d_in[7];
    const float* ww     = (const float*)d_in[8];
    const float* bw     = (const float*)d_in[9];
    const float* gamma  = (const float*)d_in[10];
    const float* beta   = (const float*)d_in[11];
    const float* bnmean = (const float*)d_in[12];
    const float* bnvar  = (const float*)d_in[13];
    float* out = (float*)d_out;

    k_prep<<<1, 256>>>(wt, wp, wc, bt, bp, gamma, beta, bnmean, bnvar, bw);
    k_scores<<<ROWS / 8, 256>>>(x);
    k_gemm_g<<<ROWS / 128, 256>>>(x, wg, bg);
    k_sort<<<BB, 1024>>>();
    k_scanA<<<dim3(NSEG, BB), 128>>>();
    k_scanB<<<1, 512>>>();
    k_final<<<ROWS / 64, 256>>>(x, ww, out);
}

// round 2
// speedup vs baseline: 1.1178x; 1.1178x over previous
#include <cuda_runtime.h>
#include <cuda_bf16.h>
#include <cstdint>

#define BB 4
#define NN 4096
#define CC 256
#define II 128
#define ROWS (BB*NN)          // 16384
#define SEG 64
#define NSEG (NN/SEG)         // 64
#define BN_EPS 1e-3f

// ---------------- scratch (static device allocations) ----------------
__device__ float d_vt[CC], d_vp[CC];
__device__ float d_ct, d_cp;
__device__ float d_scale[CC], d_shift[CC];
__device__ __nv_bfloat16 d_Wt[CC*CC];     // Wt[n][k] = (wg@ww)[k][n], bf16, k-contiguous
__device__ float d_chb[CC];               // bg @ ww
__device__ float d_h[(size_t)ROWS*CC];    // h = x@W + chb   (16 MB)
__device__ float d_st[ROWS], d_sp[ROWS];
__device__ float d_tsort[ROWS];
__device__ int   d_tidx[ROWS];
__device__ float d_Q1[(size_t)ROWS*CC];   // prefix of h_sorted      (16 MB)
__device__ float d_Q2[(size_t)ROWS*CC];   // prefix of t*h_sorted    (16 MB)
__device__ float d_seg1[BB*NSEG*CC], d_seg2[BB*NSEG*CC];
__device__ float d_off1[BB*NSEG*CC], d_off2[BB*NSEG*CC];

// ---------------- helpers ----------------------------------------------------
__device__ __forceinline__ void ldsm4(uint32_t* r, uint32_t addr) {
    asm volatile("ldmatrix.sync.aligned.m8n8.x4.shared.b16 {%0,%1,%2,%3},[%4];\n"
        : "=r"(r[0]), "=r"(r[1]), "=r"(r[2]), "=r"(r[3]) : "r"(addr));
}
__device__ __forceinline__ void mma_bf16(float* c, const uint32_t* a, uint32_t b0, uint32_t b1) {
    asm volatile("mma.sync.aligned.m16n8k16.row.col.f32.bf16.bf16.f32 "
        "{%0,%1,%2,%3},{%4,%5,%6,%7},{%8,%9},{%0,%1,%2,%3};\n"
        : "+f"(c[0]), "+f"(c[1]), "+f"(c[2]), "+f"(c[3])
        : "r"(a[0]), "r"(a[1]), "r"(a[2]), "r"(a[3]), "r"(b0), "r"(b1));
}

// ---------------- K0: fold score vectors + BN ---------------------------------
__global__ void k_prep(const float* __restrict__ wt, const float* __restrict__ wp,
                       const float* __restrict__ wc,
                       const float* __restrict__ bt, const float* __restrict__ bp,
                       const float* __restrict__ gamma, const float* __restrict__ beta,
                       const float* __restrict__ bn_mean, const float* __restrict__ bn_var,
                       const float* __restrict__ bw) {
    int c = threadIdx.x;               // 0..255
    float at = 0.f, ap = 0.f;
    #pragma unroll 4
    for (int k = 0; k < II; k++) {
        at = fmaf(wt[c*II + k], wc[k], at);
        ap = fmaf(wp[c*II + k], wc[II + k], ap);
    }
    d_vt[c] = at;
    d_vp[c] = ap;
    float a = gamma[c] * rsqrtf(bn_var[c] + BN_EPS);
    d_scale[c] = a;
    d_shift[c] = (bw[c] - bn_mean[c]) * a + beta[c];
    if (c == 0) {
        float s = 0.f;
        for (int k = 0; k < II; k++) s = fmaf(bt[k], wc[k], s);
        d_ct = s;
    }
    if (c == 1) {
        float s = 0.f;
        for (int k = 0; k < II; k++) s = fmaf(bp[k], wc[II + k], s);
        d_cp = s;
    }
}

// ---------------- K0b: W = wg@ww (fp32 -> bf16, stored transposed) ------------
__global__ __launch_bounds__(128) void k_prepW(const float* __restrict__ wg,
                                               const float* __restrict__ ww,
                                               const float* __restrict__ bg) {
    __shared__ float col[II];
    const int n = blockIdx.x;          // 0..255
    const int t = threadIdx.x;         // 0..127
    col[t] = ww[t * CC + n];
    __syncthreads();
    #pragma unroll
    for (int half = 0; half < 2; half++) {
        int c = half * 128 + t;
        float s = 0.f;
        #pragma unroll 4
        for (int j = 0; j < II; j++) s = fmaf(wg[c * II + j], col[j], s);
        d_Wt[n * CC + c] = __float2bfloat16(s);
    }
    if (t == 0) {
        float s = 0.f;
        for (int j = 0; j < II; j++) s = fmaf(bg[j], col[j], s);
        d_chb[n] = s;
    }
}

// ---------------- K1: fp32 scalar scores -------------------------------------
__global__ void k_scores(const float* __restrict__ x) {
    int row  = blockIdx.x * 8 + (threadIdx.x >> 5);
    int lane = threadIdx.x & 31;
    const float* xr = x + (size_t)row * CC;
    float at = 0.f, ap = 0.f;
    #pragma unroll
    for (int k = lane; k < CC; k += 32) {
        float v = xr[k];
        at = fmaf(v, d_vt[k], at);
        ap = fmaf(v, d_vp[k], ap);
    }
    #pragma unroll
    for (int o = 16; o; o >>= 1) {
        at += __shfl_xor_sync(0xffffffffu, at, o);
        ap += __shfl_xor_sync(0xffffffffu, ap, o);
    }
    if (lane == 0) {
        d_st[row] = at + d_ct;
        d_sp[row] = ap + d_cp;
    }
}

// ---------------- K2: h = x@W + chb  via bf16 tensor cores --------------------
// M=16384, N=256, K=256. BM=128, BN=128, BK=32. 8 warps: 4(m) x 2(n), warp 32x64.
__global__ __launch_bounds__(256) void k_gemm(const float* __restrict__ x) {
    __shared__ __nv_bfloat16 As[128][40];   // [m][k], pad to 40 (80B rows)
    __shared__ __nv_bfloat16 Bs[128][40];   // [n][k]
    const int tid  = threadIdx.x;
    const int warp = tid >> 5, lane = tid & 31;
    const int wm = warp & 3, wn = warp >> 2;
    const int r0 = blockIdx.x * 128;
    const int n0 = blockIdx.y * 128;

    float acc[2][8][4];
    #pragma unroll
    for (int ms = 0; ms < 2; ms++)
        #pragma unroll
        for (int ns = 0; ns < 8; ns++)
            #pragma unroll
            for (int q = 0; q < 4; q++) acc[ms][ns][q] = 0.f;

    const int lrow = lane & 15;
    const int lkof = (lane >> 4) << 3;

    for (int kk = 0; kk < CC; kk += 32) {
        // A tile: x[r0..r0+127][kk..kk+31] fp32 -> bf16
        #pragma unroll
        for (int p = 0; p < 4; p++) {
            int idx = p * 256 + tid;            // 1024 float4 total
            int m = idx >> 3, c = (idx & 7) * 4;
            float4 v = *(const float4*)&x[(size_t)(r0 + m) * CC + kk + c];
            __nv_bfloat162 lo = __floats2bfloat162_rn(v.x, v.y);
            __nv_bfloat162 hi = __floats2bfloat162_rn(v.z, v.w);
            uint2 pk;
            pk.x = *(uint32_t*)&lo;
            pk.y = *(uint32_t*)&hi;
            *(uint2*)&As[m][c] = pk;
        }
        // B tile: Wt[n0..n0+127][kk..kk+31] bf16 (16B vector loads)
        #pragma unroll
        for (int p = 0; p < 2; p++) {
            int idx = p * 256 + tid;            // 512 uint4 total
            int n = idx >> 2, k8 = (idx & 3) * 8;
            uint4 v = *(const uint4*)&d_Wt[(n0 + n) * CC + kk + k8];
            *(uint4*)&Bs[n][k8] = v;
        }
        __syncthreads();

        #pragma unroll
        for (int k2 = 0; k2 < 32; k2 += 16) {
            uint32_t a[2][4], b[4][4];
            #pragma unroll
            for (int ms = 0; ms < 2; ms++) {
                uint32_t ad = (uint32_t)__cvta_generic_to_shared(
                    &As[wm * 32 + ms * 16 + lrow][k2 + lkof]);
                ldsm4(a[ms], ad);
            }
            #pragma unroll
            for (int nb = 0; nb < 4; nb++) {
                uint32_t bd = (uint32_t)__cvta_generic_to_shared(
                    &Bs[wn * 64 + nb * 16 + lrow][k2 + lkof]);
                ldsm4(b[nb], bd);
            }
            #pragma unroll
            for (int ms = 0; ms < 2; ms++)
                #pragma unroll
                for (int ns = 0; ns < 8; ns++) {
                    int nb = ns >> 1, odd = ns & 1;
                    mma_bf16(acc[ms][ns], a[ms], b[nb][odd], b[nb][odd + 2]);
                }
        }
        __syncthreads();
    }

    // epilogue: h = acc + chb
    #pragma unroll
    for (int ns = 0; ns < 8; ns++) {
        int col = n0 + wn * 64 + ns * 8 + (lane & 3) * 2;
        float b0 = d_chb[col], b1 = d_chb[col + 1];
        #pragma unroll
        for (int ms = 0; ms < 2; ms++) {
            int row = r0 + wm * 32 + ms * 16 + (lane >> 2);
            float2 v0 = make_float2(acc[ms][ns][0] + b0, acc[ms][ns][1] + b1);
            float2 v1 = make_float2(acc[ms][ns][2] + b0, acc[ms][ns][3] + b1);
            *(float2*)&d_h[(size_t)row * CC + col] = v0;
            *(float2*)&d_h[(size_t)(row + 8) * CC + col] = v1;
        }
    }
}

// ---------------- K3: rank-by-counting sort (descending, tie by index) --------
__global__ __launch_bounds__(128) void k_rank() {
    __shared__ float sv[NN];            // 16 KB: whole batch
    const int b = blockIdx.y;
    const int i = blockIdx.x * 128 + threadIdx.x;   // 0..4095
    for (int j = threadIdx.x; j < NN; j += 128) sv[j] = d_st[b * NN + j];
    __syncthreads();
    const float v = sv[i];
    int rank = 0;
    const float4* s4 = (const float4*)sv;
    #pragma unroll 4
    for (int j4 = 0; j4 < NN / 4; j4++) {
        float4 m = s4[j4];
        int jb = j4 * 4;
        rank += (m.x > v) + (m.y > v) + (m.z > v) + (m.w > v);
        rank += (m.x == v && jb < i) + (m.y == v && jb + 1 < i)
              + (m.z == v && jb + 2 < i) + (m.w == v && jb + 3 < i);
    }
    d_tsort[b * NN + rank] = v;
    d_tidx [b * NN + rank] = i;
}

// ---------------- K4: segmented prefix sums of h_sorted, t*h_sorted -----------
__global__ __launch_bounds__(256) void k_scanA() {
    __shared__ int   sIdx[SEG];
    __shared__ float sT[SEG];
    const int b = blockIdx.y, s = blockIdx.x, c = threadIdx.x;
    const int base = b * NN + s * SEG;
    if (c < SEG) { sIdx[c] = d_tidx[base + c]; sT[c] = d_tsort[base + c]; }
    __syncthreads();
    float a1 = 0.f, a2 = 0.f;
    float hv = d_h[(size_t)(b * NN + sIdx[0]) * CC + c];
    #pragma unroll 4
    for (int r = 0; r < SEG; r++) {
        float hn = (r + 1 < SEG) ? d_h[(size_t)(b * NN + sIdx[r + 1]) * CC + c] : 0.f;
        a1 += hv;
        a2 = fmaf(sT[r], hv, a2);
        size_t p = (size_t)(base + r) * CC + c;
        d_Q1[p] = a1;
        d_Q2[p] = a2;
        hv = hn;
    }
    int o = (b * NSEG + s) * CC + c;
    d_seg1[o] = a1;
    d_seg2[o] = a2;
}

// ---------------- K5: exclusive scan of segment totals ------------------------
__global__ __launch_bounds__(256) void k_scanB() {
    const int b = blockIdx.x, c = threadIdx.x;
    float a1 = 0.f, a2 = 0.f;
    for (int s = 0; s < NSEG; s++) {
        int idx = (b * NSEG + s) * CC + c;
        d_off1[idx] = a1;
        d_off2[idx] = a2;
        a1 += d_seg1[idx];
        a2 += d_seg2[idx];
    }
}

// ---------------- K6: streaming output ----------------------------------------
// out[i,c] = scale[c]*((sp_i*Q1[k_i-1,c] + Q2[k_i-1,c])/N) + shift[c] + x[i,c]
__global__ __launch_bounds__(256) void k_out(const float* __restrict__ x,
                                             float* __restrict__ out) {
    __shared__ float sps[32];
    __shared__ int   ks[32];
    const int gr0 = blockIdx.x * 32;
    const int b   = gr0 / NN;
    const int tid = threadIdx.x;
    if (tid < 32) {
        int i = gr0 + tid;
        float sp = d_sp[i];
        sps[tid] = sp;
        float tau = -sp;
        const float* ts = d_tsort + b * NN;
        int lo = 0, hi = NN;
        while (lo < hi) {
            int mid = (lo + hi) >> 1;
            if (ts[mid] > tau) lo = mid + 1; else hi = mid;
        }
        ks[tid] = lo;
    }
    __syncthreads();
    const float invn = 1.f / NN;
    const int c = tid;
    const float sc = d_scale[c], sh = d_shift[c];
    #pragma unroll 2
    for (int rr = 0; rr < 32; rr++) {
        int i = gr0 + rr;
        int k = ks[rr];
        float q1 = 0.f, q2 = 0.f;
        if (k > 0) {
            size_t p  = (size_t)(b * NN + k - 1) * CC + c;
            int    so = (b * NSEG + ((k - 1) >> 6)) * CC + c;
            q1 = d_Q1[p] + d_off1[so];
            q2 = d_Q2[p] + d_off2[so];
        }
        float y = (sps[rr] * q1 + q2) * invn;
        size_t gi = (size_t)i * CC + c;
        out[gi] = fmaf(y, sc, sh) + x[gi];
    }
}

// ---------------- launch -----------------------------------------------------
extern "C" void kernel_launch(void* const* d_in, const int* in_sizes, int n_in,
                              void* d_out, int out_size) {
    const float* x      = (const float*)d_in[0];
    const float* wg     = (const float*)d_in[1];
    const float* bg     = (const float*)d_in[2];
    const float* wt     = (const float*)d_in[3];
    const float* bt     = (const float*)d_in[4];
    const float* wp     = (const float*)d_in[5];
    const float* bp     = (const float*)d_in[6];
    const float* wc     = (const float*)d_in[7];
    const float* ww     = (const float*)d_in[8];
    const float* bw     = (const float*)d_in[9];
    const float* gamma  = (const float*)d_in[10];
    const float* beta   = (const float*)d_in[11];
    const float* bnmean = (const float*)d_in[12];
    const float* bnvar  = (const float*)d_in[13];
    float* out = (float*)d_out;

    k_prep<<<1, 256>>>(wt, wp, wc, bt, bp, gamma, beta, bnmean, bnvar, bw);
    k_prepW<<<CC, 128>>>(wg, ww, bg);
    k_scores<<<ROWS / 8, 256>>>(x);
    k_gemm<<<dim3(ROWS / 128, 2), 256>>>(x);
    k_rank<<<dim3(NN / 128, BB), 128>>>();
    k_scanA<<<dim3(NSEG, BB), 256>>>();
    k_scanB<<<BB, 256>>>();
    k_out<<<ROWS / 32, 256>>>(x, out);
}

// round 3
// speedup vs baseline: 1.3902x; 1.2437x over previous
#include <cuda_runtime.h>
#include <cuda_bf16.h>
#include <cstdint>

#define BB 4
#define NN 4096
#define CC 256
#define II 128
#define ROWS (BB*NN)          // 16384
#define SEG 32
#define NSEG (NN/SEG)         // 128
#define BN_EPS 1e-3f

// ---------------- scratch (static device allocations) ----------------
__device__ float d_vt[CC], d_vp[CC];
__device__ float d_ct, d_cp;
__device__ float d_scale[CC], d_shift[CC];
__device__ __nv_bfloat16 d_Wt[CC*CC];       // Wt[n][k] = (wg@ww)[k][n], bf16
__device__ float d_chb[CC];                 // bg @ ww
__device__ float d_h[(size_t)ROWS*CC];      // h = x@W + chb   (16 MB)
__device__ float d_st[ROWS], d_sp[ROWS];
__device__ float d_tsort[ROWS];
__device__ int   d_tidx[ROWS];
__device__ float2 d_Q[(size_t)ROWS*CC];     // (prefix h, prefix t*h)   (32 MB)
__device__ float2 d_seg[BB*NSEG*CC];        // segment totals
__device__ float2 d_off[BB*NSEG*CC];        // exclusive segment offsets

// ---------------- helpers ----------------------------------------------------
__device__ __forceinline__ void ldsm4(uint32_t* r, uint32_t addr) {
    asm volatile("ldmatrix.sync.aligned.m8n8.x4.shared.b16 {%0,%1,%2,%3},[%4];\n"
        : "=r"(r[0]), "=r"(r[1]), "=r"(r[2]), "=r"(r[3]) : "r"(addr));
}
__device__ __forceinline__ void mma_bf16(float* c, const uint32_t* a, uint32_t b0, uint32_t b1) {
    asm volatile("mma.sync.aligned.m16n8k16.row.col.f32.bf16.bf16.f32 "
        "{%0,%1,%2,%3},{%4,%5,%6,%7},{%8,%9},{%0,%1,%2,%3};\n"
        : "+f"(c[0]), "+f"(c[1]), "+f"(c[2]), "+f"(c[3])
        : "r"(a[0]), "r"(a[1]), "r"(a[2]), "r"(a[3]), "r"(b0), "r"(b1));
}

// ---------------- K0: W = wg@ww (bf16, transposed) + all weight folds ---------
__global__ __launch_bounds__(128) void k_prep(const float* __restrict__ wg,
                                              const float* __restrict__ ww,
                                              const float* __restrict__ bg,
                                              const float* __restrict__ wt,
                                              const float* __restrict__ wp,
                                              const float* __restrict__ wc,
                                              const float* __restrict__ bt,
                                              const float* __restrict__ bp,
                                              const float* __restrict__ gamma,
                                              const float* __restrict__ beta,
                                              const float* __restrict__ bn_mean,
                                              const float* __restrict__ bn_var,
                                              const float* __restrict__ bw) {
    __shared__ float col[II];
    const int n = blockIdx.x;          // 0..255
    const int t = threadIdx.x;         // 0..127
    col[t] = ww[t * CC + n];
    __syncthreads();
    #pragma unroll
    for (int half = 0; half < 2; half++) {
        int c = half * 128 + t;
        float s = 0.f;
        #pragma unroll 4
        for (int j = 0; j < II; j++) s = fmaf(wg[c * II + j], col[j], s);
        d_Wt[n * CC + c] = __float2bfloat16(s);
    }
    if (t == 0) {
        float s = 0.f;
        for (int j = 0; j < II; j++) s = fmaf(bg[j], col[j], s);
        d_chb[n] = s;
    }
    if (t == 1) {
        float s = 0.f;
        for (int k = 0; k < II; k++) s = fmaf(wt[n * II + k], wc[k], s);
        d_vt[n] = s;
    }
    if (t == 2) {
        float s = 0.f;
        for (int k = 0; k < II; k++) s = fmaf(wp[n * II + k], wc[II + k], s);
        d_vp[n] = s;
    }
    if (t == 3) {
        float a = gamma[n] * rsqrtf(bn_var[n] + BN_EPS);
        d_scale[n] = a;
        d_shift[n] = (bw[n] - bn_mean[n]) * a + beta[n];
    }
    if (n == 0 && t == 4) {
        float s = 0.f;
        for (int k = 0; k < II; k++) s = fmaf(bt[k], wc[k], s);
        d_ct = s;
    }
    if (n == 0 && t == 5) {
        float s = 0.f;
        for (int k = 0; k < II; k++) s = fmaf(bp[k], wc[II + k], s);
        d_cp = s;
    }
}

// ---------------- K1: fp32 scalar scores -------------------------------------
__global__ void k_scores(const float* __restrict__ x) {
    int row  = blockIdx.x * 8 + (threadIdx.x >> 5);
    int lane = threadIdx.x & 31;
    const float* xr = x + (size_t)row * CC;
    float at = 0.f, ap = 0.f;
    #pragma unroll
    for (int k = lane; k < CC; k += 32) {
        float v = xr[k];
        at = fmaf(v, d_vt[k], at);
        ap = fmaf(v, d_vp[k], ap);
    }
    #pragma unroll
    for (int o = 16; o; o >>= 1) {
        at += __shfl_xor_sync(0xffffffffu, at, o);
        ap += __shfl_xor_sync(0xffffffffu, ap, o);
    }
    if (lane == 0) {
        d_st[row] = at + d_ct;
        d_sp[row] = ap + d_cp;
    }
}

// ---------------- K2: h = x@W + chb  (bf16 MMA, double-buffered) --------------
// M=16384, N=256, K=256. BM=128, BN=128, BK=32. 8 warps: 4(m) x 2(n).
__global__ __launch_bounds__(256) void k_gemm(const float* __restrict__ x) {
    __shared__ __nv_bfloat16 As[2][128][40];   // [m][k], padded rows
    __shared__ __nv_bfloat16 Bs[2][128][40];   // [n][k]
    const int tid  = threadIdx.x;
    const int warp = tid >> 5, lane = tid & 31;
    const int wm = warp & 3, wn = warp >> 2;
    const int r0 = blockIdx.x * 128;
    const int n0 = blockIdx.y * 128;

    float acc[2][8][4];
    #pragma unroll
    for (int ms = 0; ms < 2; ms++)
        #pragma unroll
        for (int ns = 0; ns < 8; ns++)
            #pragma unroll
            for (int q = 0; q < 4; q++) acc[ms][ns][q] = 0.f;

    const int am = tid >> 1, ac = (tid & 1) * 16;      // A: 2 float4 rows? no:
    // A tile addressing: 1024 float4 loads; thread handles 4 (p*256+tid)
    const int lrow = lane & 15;
    const int lkof = (lane >> 4) << 3;

    // ---- prologue: tile 0 straight to smem buffer 0 ----
    #pragma unroll
    for (int p = 0; p < 4; p++) {
        int idx = p * 256 + tid;
        int m = idx >> 3, c = (idx & 7) * 4;
        float4 v = *(const float4*)&x[(size_t)(r0 + m) * CC + c];
        __nv_bfloat162 lo = __floats2bfloat162_rn(v.x, v.y);
        __nv_bfloat162 hi = __floats2bfloat162_rn(v.z, v.w);
        uint2 pk; pk.x = *(uint32_t*)&lo; pk.y = *(uint32_t*)&hi;
        *(uint2*)&As[0][m][c] = pk;
    }
    #pragma unroll
    for (int p = 0; p < 2; p++) {
        int idx = p * 256 + tid;
        int nn = idx >> 2, k8 = (idx & 3) * 8;
        *(uint4*)&Bs[0][nn][k8] = *(const uint4*)&d_Wt[(n0 + nn) * CC + k8];
    }
    __syncthreads();

    #pragma unroll
    for (int t = 0; t < 8; t++) {
        const int pb = t & 1;
        float4 ra[4]; uint4 rb[2];
        if (t < 7) {
            const int kk = (t + 1) * 32;
            #pragma unroll
            for (int p = 0; p < 4; p++) {
                int idx = p * 256 + tid;
                int m = idx >> 3, c = (idx & 7) * 4;
                ra[p] = *(const float4*)&x[(size_t)(r0 + m) * CC + kk + c];
            }
            #pragma unroll
            for (int p = 0; p < 2; p++) {
                int idx = p * 256 + tid;
                int nn = idx >> 2, k8 = (idx & 3) * 8;
                rb[p] = *(const uint4*)&d_Wt[(n0 + nn) * CC + kk + k8];
            }
        }

        #pragma unroll
        for (int k2 = 0; k2 < 32; k2 += 16) {
            uint32_t a[2][4], b[4][4];
            #pragma unroll
            for (int ms = 0; ms < 2; ms++) {
                uint32_t ad = (uint32_t)__cvta_generic_to_shared(
                    &As[pb][wm * 32 + ms * 16 + lrow][k2 + lkof]);
                ldsm4(a[ms], ad);
            }
            #pragma unroll
            for (int nb = 0; nb < 4; nb++) {
                uint32_t bd = (uint32_t)__cvta_generic_to_shared(
                    &Bs[pb][wn * 64 + nb * 16 + lrow][k2 + lkof]);
                ldsm4(b[nb], bd);
            }
            #pragma unroll
            for (int ms = 0; ms < 2; ms++)
                #pragma unroll
                for (int ns = 0; ns < 8; ns++) {
                    int nb = ns >> 1, odd = ns & 1;
                    mma_bf16(acc[ms][ns], a[ms], b[nb][odd], b[nb][odd + 2]);
                }
        }

        if (t < 7) {
            const int pn = pb ^ 1;
            #pragma unroll
            for (int p = 0; p < 4; p++) {
                int idx = p * 256 + tid;
                int m = idx >> 3, c = (idx & 7) * 4;
                __nv_bfloat162 lo = __floats2bfloat162_rn(ra[p].x, ra[p].y);
                __nv_bfloat162 hi = __floats2bfloat162_rn(ra[p].z, ra[p].w);
                uint2 pk; pk.x = *(uint32_t*)&lo; pk.y = *(uint32_t*)&hi;
                *(uint2*)&As[pn][m][c] = pk;
            }
            #pragma unroll
            for (int p = 0; p < 2; p++) {
                int idx = p * 256 + tid;
                int nn = idx >> 2, k8 = (idx & 3) * 8;
                *(uint4*)&Bs[pn][nn][k8] = rb[p];
            }
        }
        __syncthreads();
    }

    // epilogue: h = acc + chb
    #pragma unroll
    for (int ns = 0; ns < 8; ns++) {
        int col = n0 + wn * 64 + ns * 8 + (lane & 3) * 2;
        float b0 = d_chb[col], b1 = d_chb[col + 1];
        #pragma unroll
        for (int ms = 0; ms < 2; ms++) {
            int row = r0 + wm * 32 + ms * 16 + (lane >> 2);
            *(float2*)&d_h[(size_t)row * CC + col] =
                make_float2(acc[ms][ns][0] + b0, acc[ms][ns][1] + b1);
            *(float2*)&d_h[(size_t)(row + 8) * CC + col] =
                make_float2(acc[ms][ns][2] + b0, acc[ms][ns][3] + b1);
        }
    }
}

// ---------------- K3: rank-by-counting sort (descending, tie by index) --------
__global__ __launch_bounds__(128) void k_rank() {
    __shared__ float sv[NN];            // 16 KB
    const int b = blockIdx.y;
    const int i = blockIdx.x * 128 + threadIdx.x;
    for (int j = threadIdx.x; j < NN; j += 128) sv[j] = d_st[b * NN + j];
    __syncthreads();
    const float v = sv[i];
    int rank = 0;
    const float4* s4 = (const float4*)sv;
    #pragma unroll 4
    for (int j4 = 0; j4 < NN / 4; j4++) {
        float4 m = s4[j4];
        int jb = j4 * 4;
        rank += (m.x > v) + (m.y > v) + (m.z > v) + (m.w > v);
        rank += (m.x == v && jb < i) + (m.y == v && jb + 1 < i)
              + (m.z == v && jb + 2 < i) + (m.w == v && jb + 3 < i);
    }
    d_tsort[b * NN + rank] = v;
    d_tidx [b * NN + rank] = i;
}

// ---------------- K4: segmented prefix sums (batch-load then scan) ------------
__global__ __launch_bounds__(256) void k_scanA() {
    __shared__ int   sIdx[SEG];
    __shared__ float sT[SEG];
    const int b = blockIdx.y, s = blockIdx.x, c = threadIdx.x;
    const int base = b * NN + s * SEG;
    if (c < SEG) { sIdx[c] = d_tidx[base + c]; sT[c] = d_tsort[base + c]; }
    __syncthreads();
    // issue all 32 gather loads up-front (MLP=32)
    float hv[SEG];
    #pragma unroll
    for (int r = 0; r < SEG; r++)
        hv[r] = d_h[(size_t)(b * NN + sIdx[r]) * CC + c];
    float a1 = 0.f, a2 = 0.f;
    #pragma unroll
    for (int r = 0; r < SEG; r++) {
        a1 += hv[r];
        a2 = fmaf(sT[r], hv[r], a2);
        d_Q[(size_t)(base + r) * CC + c] = make_float2(a1, a2);
    }
    d_seg[(b * NSEG + s) * CC + c] = make_float2(a1, a2);
}

// ---------------- K5: exclusive scan of segment totals ------------------------
__global__ __launch_bounds__(256) void k_scanB() {
    const int b = blockIdx.x, c = threadIdx.x;
    float a1 = 0.f, a2 = 0.f;
    #pragma unroll 4
    for (int s = 0; s < NSEG; s++) {
        int idx = (b * NSEG + s) * CC + c;
        float2 v = d_seg[idx];
        d_off[idx] = make_float2(a1, a2);
        a1 += v.x;
        a2 += v.y;
    }
}

// ---------------- K6: streaming output ----------------------------------------
__global__ __launch_bounds__(256) void k_out(const float* __restrict__ x,
                                             float* __restrict__ out) {
    __shared__ float sps[32];
    __shared__ int   ks[32];
    const int gr0 = blockIdx.x * 32;
    const int b   = gr0 / NN;
    const int tid = threadIdx.x;
    if (tid < 32) {
        int i = gr0 + tid;
        float sp = d_sp[i];
        sps[tid] = sp;
        float tau = -sp;
        const float* ts = d_tsort + b * NN;
        int lo = 0, hi = NN;
        while (lo < hi) {
            int mid = (lo + hi) >> 1;
            if (ts[mid] > tau) lo = mid + 1; else hi = mid;
        }
        ks[tid] = lo;
    }
    __syncthreads();
    const float invn = 1.f / NN;
    const int c = tid;
    const float sc = d_scale[c], sh = d_shift[c];
    #pragma unroll 4
    for (int rr = 0; rr < 32; rr++) {
        int i = gr0 + rr;
        int k = ks[rr];
        float q1 = 0.f, q2 = 0.f;
        if (k > 0) {
            float2 q = d_Q[(size_t)(b * NN + k - 1) * CC + c];
            float2 o = d_off[(b * NSEG + ((k - 1) >> 5)) * CC + c];
            q1 = q.x + o.x;
            q2 = q.y + o.y;
        }
        float y = (sps[rr] * q1 + q2) * invn;
        size_t gi = (size_t)i * CC + c;
        out[gi] = fmaf(y, sc, sh) + x[gi];
    }
}

// ---------------- launch -----------------------------------------------------
extern "C" void kernel_launch(void* const* d_in, const int* in_sizes, int n_in,
                              void* d_out, int out_size) {
    const float* x      = (const float*)d_in[0];
    const float* wg     = (const float*)d_in[1];
    const float* bg     = (const float*)d_in[2];
    const float* wt     = (const float*)d_in[3];
    const float* bt     = (const float*)d_in[4];
    const float* wp     = (const float*)d_in[5];
    const float* bp     = (const float*)d_in[6];
    const float* wc     = (const float*)d_in[7];
    const float* ww     = (const float*)d_in[8];
    const float* bw     = (const float*)d_in[9];
    const float* gamma  = (const float*)d_in[10];
    const float* beta   = (const float*)d_in[11];
    const float* bnmean = (const float*)d_in[12];
    const float* bnvar  = (const float*)d_in[13];
    float* out = (float*)d_out;

    k_prep<<<CC, 128>>>(wg, ww, bg, wt, wp, wc, bt, bp, gamma, beta, bnmean, bnvar, bw);
    k_scores<<<ROWS / 8, 256>>>(x);
    k_gemm<<<dim3(ROWS / 128, 2), 256>>>(x);
    k_rank<<<dim3(NN / 128, BB), 128>>>();
    k_scanA<<<dim3(NSEG, BB), 256>>>();
    k_scanB<<<BB, 256>>>();
    k_out<<<ROWS / 32, 256>>>(x, out);
}